// round 12
// baseline (speedup 1.0000x reference)
#include <cuda_runtime.h>
#include <math.h>
#include <stdint.h>

#define TPB 256

// per-image smem block (floats), stride IMG
#define F_OFF     0        // 6*16*16  = 1536
#define RPAD_OFF  1536     // 6*14*14  = 1176
#define HPAD_OFF  2712     // 48*14*14 = 9408
#define ZPART_OFF 12120    // 8*6*144  = 6912
#define ZBUF_OFF  19032    // 6*144    = 864
#define IMG       19896    // per-image stride
// shared weights after the two image blocks
#define W1T_OFF   39792    // 54*48 = 2592 (16B aligned)
#define W2S_OFF   42384    // 432*8 = 3456 (16B aligned)
#define B1S_OFF   45840    // 48
#define B2S_OFF   45888    // 8
#define SMEM_FLOATS 45896
#define SMEM_BYTES (SMEM_FLOATS * 4)   // 183584 <= 227KB -> 1 CTA/SM

__constant__ int      c_hw[8]   = {1, 2, 4, 6, 8, 10, 12, 16};
__constant__ int      c_off[8]  = {0, 6, 30, 126, 342, 726, 1326, 2190};
// ceil(2^32/d); sentinel 0 for d==1
__constant__ uint32_t c_mhw[8]  = {0u, 2147483648u, 1073741824u, 715827883u,
                                   536870912u, 429496730u, 357913942u, 268435456u};
__constant__ uint32_t c_mnpx[8] = {0u, 1073741824u, 268435456u, 119304648u,
                                   67108864u, 42949673u, 29826162u, 16777216u};
// nq = npx/2: {-,2,8,18,32,50,72,-}
__constant__ uint32_t c_mnq[8]  = {0u, 2147483648u, 536870912u, 238609295u,
                                   134217728u, 85899346u, 59652324u, 0u};

// XLA's fp32 tanh rational approximation
__device__ __forceinline__ float tanh_xla(float x) {
    float cx = fminf(fmaxf(x, -7.90531110763549805f), 7.90531110763549805f);
    float x2 = cx * cx;
    float np_ = fmaf(-2.76076847742355e-16f, x2, 2.00018790482477e-13f);
    np_ = fmaf(np_, x2, -8.60467152213735e-11f);
    np_ = fmaf(np_, x2, 5.12229709037114e-08f);
    np_ = fmaf(np_, x2, 1.48572235717979e-05f);
    np_ = fmaf(np_, x2, 6.37261928875436e-04f);
    np_ = fmaf(np_, x2, 4.89352455891786e-03f);
    float num = cx * np_;
    float dp_ = fmaf(1.19825839466702e-06f, x2, 1.18534705686654e-04f);
    dp_ = fmaf(dp_, x2, 2.26843463243900e-03f);
    dp_ = fmaf(dp_, x2, 4.89352518554385e-03f);
    float r = num / dp_;
    return (fabsf(x) < 0.0004f) ? x : r;
}

__device__ __forceinline__ float gelu_exact(float h) {
    return 0.5f * h * (1.0f + erff(h * 0.70710678118654752f));
}

__global__ void __launch_bounds__(TPB) var_tok_kernel(
    const float* __restrict__ latents, const float* __restrict__ w1,
    const float* __restrict__ b1, const float* __restrict__ w2,
    const float* __restrict__ b2, float* __restrict__ out)
{
    extern __shared__ float sm[];
    const int tid = threadIdx.x;

    const float halfl8 = (8.0f - 1.0f) * (1.0f + 1e-3f) / 2.0f;
    const float shift8 = atanhf(0.5f / halfl8);
    const float halfl5 = (5.0f - 1.0f) * (1.0f + 1e-3f) / 2.0f;

    const float* lat0 = latents + (size_t)blockIdx.x * 3072;
    const float* lat1 = lat0 + 1536;
    float* outb0 = out + (size_t)blockIdx.x * 7452;
    float* outb1 = outb0 + 3726;

    for (int i = tid; i < 1536; i += TPB) {
        sm[F_OFF + i]       = lat0[i];
        sm[IMG + F_OFF + i] = lat1[i];
    }

    for (int s = 0; s < 8; s++) {
        const int hw  = c_hw[s];
        const int npx = hw * hw;
        const int W2  = hw + 2;
        const int w22 = W2 * W2;
        const uint32_t mhw  = c_mhw[s];
        const uint32_t mnpx = c_mnpx[s];
        const bool last = (s == 7);

        // ---- stage 0: zero padded buffers (both images), stage weights ----
        if (!last) {
            if (hw > 1) {
                for (int i = tid; i < 6 * w22;  i += TPB) {
                    sm[RPAD_OFF + i] = 0.0f; sm[IMG + RPAD_OFF + i] = 0.0f;
                }
                for (int i = tid; i < 48 * w22; i += TPB) {
                    sm[HPAD_OFF + i] = 0.0f; sm[IMG + HPAD_OFF + i] = 0.0f;
                }
            }
            const float* w1g = w1 + s * 2592;       // [48][54]
            for (int i = tid; i < 2592; i += TPB) {
                int oc = i / 54; int j = i - oc * 54;
                sm[W1T_OFF + j * 48 + oc] = w1g[i];  // -> [54][48]
            }
            const float* w2g = w2 + s * 2592;       // [6][432]
            for (int i = tid; i < 2592; i += TPB) {
                int oc = i / 432; int j = i - oc * 432;
                sm[W2S_OFF + j * 8 + oc] = w2g[i];   // -> [432][8pad]
            }
            if (tid < 48) sm[B1S_OFF + tid] = b1[s * 48 + tid];
            if (tid < 6)  sm[B2S_OFF + tid] = b2[s * 6 + tid];
        }
        __syncthreads();

        // ---- Phase A: downsample -> FSQ quantize -> out (+ rpad), both imgs ----
        {
            const float sc = 16.0f / (float)hw;
            float* ob0 = outb0 + c_off[s];
            float* ob1 = outb1 + c_off[s];
            const int n = 6 * npx;
            for (int idx = tid; idx < n; idx += TPB) {
                int c, p;
                if (npx == 1) { c = idx; p = 0; }
                else { c = (int)__umulhi((unsigned)idx, mnpx); p = idx - c * npx; }
                int oy, ox;
                if (hw == 1) { oy = 0; ox = 0; }
                else { oy = (int)__umulhi((unsigned)p, mhw); ox = p - oy * hw; }
                float sy = __fadd_rn(__fmul_rn((float)oy + 0.5f, sc), -0.5f);
                float sx = __fadd_rn(__fmul_rn((float)ox + 0.5f, sc), -0.5f);
                float fy = floorf(sy), fx = floorf(sx);
                float wy = sy - fy,  wx = sx - fx;
                int y0 = (int)fy, x0 = (int)fx;
                int ya = min(max(y0, 0), 15),     yb = min(max(y0 + 1, 0), 15);
                int xa = min(max(x0, 0), 15),     xb = min(max(x0 + 1, 0), 15);
                int i00 = ya * 16 + xa, i01 = ya * 16 + xb;
                int i10 = yb * 16 + xa, i11 = yb * 16 + xb;
                int rp = RPAD_OFF + c * w22 + (oy + 1) * W2 + (ox + 1);
                #pragma unroll
                for (int im = 0; im < 2; im++) {
                    const float* fc = sm + im * IMG + F_OFF + (c << 8);
                    float v00 = fc[i00], v01 = fc[i01];
                    float v10 = fc[i10], v11 = fc[i11];
                    float va = __fadd_rn(__fmul_rn(v00, 1.0f - wx), __fmul_rn(v01, wx));
                    float vb = __fadd_rn(__fmul_rn(v10, 1.0f - wx), __fmul_rn(v11, wx));
                    float v  = __fadd_rn(__fmul_rn(va, 1.0f - wy), __fmul_rn(vb, wy));
                    float q;
                    if (c < 3) {
                        float bnd = __fadd_rn(__fmul_rn(tanh_xla(v + shift8), halfl8), -0.5f);
                        q = rintf(bnd) * 0.25f;
                    } else {
                        float bnd = __fmul_rn(tanh_xla(v), halfl5);
                        q = rintf(bnd) * 0.5f;
                    }
                    (im ? ob1 : ob0)[idx] = q;
                    if (!last) sm[im * IMG + rp] = q;
                }
            }
        }
        if (last) break;
        __syncthreads();

        // ---- conv1 (6->48) + GELU: tasks = (y-pair, oc-group-of-8), both imgs ----
        // Per-output fmaf order: ic -> ky -> kx  (bit-identical to R2)
        if (hw == 1) {
            if (tid < 96) {
                int im = tid / 48, oc = tid - im * 48;
                const float* b = sm + im * IMG;
                float a = 0.0f;
                #pragma unroll
                for (int ic = 0; ic < 6; ic++)
                    a = fmaf(b[RPAD_OFF + ic * 9 + 4],
                             sm[W1T_OFF + (ic * 9 + 4) * 48 + oc], a);
                sm[im * IMG + HPAD_OFF + oc * 9 + 4] = gelu_exact(a + sm[B1S_OFF + oc]);
            }
        } else {
            const int nq = npx >> 1;
            const int ntask = 6 * nq;
            const uint32_t mnq = c_mnq[s];
            for (int t = tid; t < ntask; t += TPB) {
                int g  = (int)__umulhi((unsigned)t, mnq);
                int q  = t - g * nq;
                int y2 = (int)__umulhi((unsigned)q, mhw);
                int x  = q - y2 * hw;
                int y  = y2 * 2;
                float acc0[16], acc1[16];
                #pragma unroll
                for (int i = 0; i < 16; i++) { acc0[i] = 0.0f; acc1[i] = 0.0f; }
                const float* wbase = sm + W1T_OFF + g * 8;
                for (int ic = 0; ic < 6; ic++) {
                    int ro = RPAD_OFF + ic * w22 + y * W2 + x;
                    const float* rr0 = sm + ro;
                    const float* rr1 = sm + IMG + ro;
                    float rv0[4][3], rv1[4][3];
                    #pragma unroll
                    for (int kx = 0; kx < 3; kx++) {
                        rv0[0][kx] = rr0[kx];          rv1[0][kx] = rr1[kx];
                        rv0[1][kx] = rr0[W2 + kx];     rv1[1][kx] = rr1[W2 + kx];
                        rv0[2][kx] = rr0[2 * W2 + kx]; rv1[2][kx] = rr1[2 * W2 + kx];
                        rv0[3][kx] = rr0[3 * W2 + kx]; rv1[3][kx] = rr1[3 * W2 + kx];
                    }
                    const float* wr = wbase + ic * 432;
                    #pragma unroll
                    for (int ky = 0; ky < 3; ky++) {
                        #pragma unroll
                        for (int kx = 0; kx < 3; kx++) {
                            const float* wk = wr + (ky * 3 + kx) * 48;
                            float4 wa = *(const float4*)(wk);
                            float4 wb = *(const float4*)(wk + 4);
                            float a0 = rv0[ky][kx], a1 = rv0[ky + 1][kx];
                            float b0 = rv1[ky][kx], b1v = rv1[ky + 1][kx];
                            acc0[0]  = fmaf(a0, wa.x, acc0[0]);
                            acc0[1]  = fmaf(a0, wa.y, acc0[1]);
                            acc0[2]  = fmaf(a0, wa.z, acc0[2]);
                            acc0[3]  = fmaf(a0, wa.w, acc0[3]);
                            acc0[4]  = fmaf(a0, wb.x, acc0[4]);
                            acc0[5]  = fmaf(a0, wb.y, acc0[5]);
                            acc0[6]  = fmaf(a0, wb.z, acc0[6]);
                            acc0[7]  = fmaf(a0, wb.w, acc0[7]);
                            acc0[8]  = fmaf(a1, wa.x, acc0[8]);
                            acc0[9]  = fmaf(a1, wa.y, acc0[9]);
                            acc0[10] = fmaf(a1, wa.z, acc0[10]);
                            acc0[11] = fmaf(a1, wa.w, acc0[11]);
                            acc0[12] = fmaf(a1, wb.x, acc0[12]);
                            acc0[13] = fmaf(a1, wb.y, acc0[13]);
                            acc0[14] = fmaf(a1, wb.z, acc0[14]);
                            acc0[15] = fmaf(a1, wb.w, acc0[15]);
                            acc1[0]  = fmaf(b0, wa.x, acc1[0]);
                            acc1[1]  = fmaf(b0, wa.y, acc1[1]);
                            acc1[2]  = fmaf(b0, wa.z, acc1[2]);
                            acc1[3]  = fmaf(b0, wa.w, acc1[3]);
                            acc1[4]  = fmaf(b0, wb.x, acc1[4]);
                            acc1[5]  = fmaf(b0, wb.y, acc1[5]);
                            acc1[6]  = fmaf(b0, wb.z, acc1[6]);
                            acc1[7]  = fmaf(b0, wb.w, acc1[7]);
                            acc1[8]  = fmaf(b1v, wa.x, acc1[8]);
                            acc1[9]  = fmaf(b1v, wa.y, acc1[9]);
                            acc1[10] = fmaf(b1v, wa.z, acc1[10]);
                            acc1[11] = fmaf(b1v, wa.w, acc1[11]);
                            acc1[12] = fmaf(b1v, wb.x, acc1[12]);
                            acc1[13] = fmaf(b1v, wb.y, acc1[13]);
                            acc1[14] = fmaf(b1v, wb.z, acc1[14]);
                            acc1[15] = fmaf(b1v, wb.w, acc1[15]);
                        }
                    }
                }
                int hp0 = HPAD_OFF + (y + 1) * W2 + (x + 1);
                int oc0 = g * 8;
                #pragma unroll
                for (int j = 0; j < 8; j++) {
                    float bj = sm[B1S_OFF + oc0 + j];
                    int o = hp0 + (oc0 + j) * w22;
                    sm[o]            = gelu_exact(acc0[j] + bj);
                    sm[o + W2]       = gelu_exact(acc0[8 + j] + bj);
                    sm[IMG + o]      = gelu_exact(acc1[j] + bj);
                    sm[IMG + o + W2] = gelu_exact(acc1[8 + j] + bj);
                }
            }
        }
        __syncthreads();

        // ---- conv2 (48->6): tasks = (y-pair, ic-group-of-SIX), both imgs ----
        if (hw == 1) {
            if (tid < 12) {
                int im = tid / 6, oc = tid - im * 6;
                const float* b = sm + im * IMG;
                float sum = sm[B2S_OFF + oc];
                #pragma unroll
                for (int g = 0; g < 8; g++) {
                    float a = 0.0f;
                    #pragma unroll
                    for (int icl = 0; icl < 6; icl++) {
                        int ic = g * 6 + icl;
                        a = fmaf(b[HPAD_OFF + ic * 9 + 4],
                                 sm[W2S_OFF + ic * 72 + 32 + oc], a);
                    }
                    sum += a;
                }
                sm[im * IMG + ZBUF_OFF + oc] = sum;
            }
            __syncthreads();
        } else {
            const int nq = npx >> 1;
            const int ntask = 8 * nq;
            const uint32_t mnq = c_mnq[s];
            for (int t = tid; t < ntask; t += TPB) {
                int g  = (int)__umulhi((unsigned)t, mnq);
                int q  = t - g * nq;
                int y2 = (int)__umulhi((unsigned)q, mhw);
                int x  = q - y2 * hw;
                int y  = y2 * 2;
                float acc0[12], acc1[12];
                #pragma unroll
                for (int i = 0; i < 12; i++) { acc0[i] = 0.0f; acc1[i] = 0.0f; }
                #pragma unroll
                for (int icl = 0; icl < 6; icl++) {
                    int ic = g * 6 + icl;
                    int ho = HPAD_OFF + ic * w22 + y * W2 + x;
                    const float* hr0 = sm + ho;
                    const float* hr1 = sm + IMG + ho;
                    float hv0[4][3], hv1[4][3];
                    #pragma unroll
                    for (int kx = 0; kx < 3; kx++) {
                        hv0[0][kx] = hr0[kx];          hv1[0][kx] = hr1[kx];
                        hv0[1][kx] = hr0[W2 + kx];     hv1[1][kx] = hr1[W2 + kx];
                        hv0[2][kx] = hr0[2 * W2 + kx]; hv1[2][kx] = hr1[2 * W2 + kx];
                        hv0[3][kx] = hr0[3 * W2 + kx]; hv1[3][kx] = hr1[3 * W2 + kx];
                    }
                    const float* wr = sm + W2S_OFF + ic * 72;
                    #pragma unroll
                    for (int ky = 0; ky < 3; ky++) {
                        #pragma unroll
                        for (int kx = 0; kx < 3; kx++) {
                            const float* wk = wr + (ky * 3 + kx) * 8;
                            float4 wa = *(const float4*)(wk);
                            float2 wb = *(const float2*)(wk + 4);
                            float a0 = hv0[ky][kx], a1 = hv0[ky + 1][kx];
                            float b0 = hv1[ky][kx], b1v = hv1[ky + 1][kx];
                            acc0[0]  = fmaf(a0, wa.x, acc0[0]);
                            acc0[1]  = fmaf(a0, wa.y, acc0[1]);
                            acc0[2]  = fmaf(a0, wa.z, acc0[2]);
                            acc0[3]  = fmaf(a0, wa.w, acc0[3]);
                            acc0[4]  = fmaf(a0, wb.x, acc0[4]);
                            acc0[5]  = fmaf(a0, wb.y, acc0[5]);
                            acc0[6]  = fmaf(a1, wa.x, acc0[6]);
                            acc0[7]  = fmaf(a1, wa.y, acc0[7]);
                            acc0[8]  = fmaf(a1, wa.z, acc0[8]);
                            acc0[9]  = fmaf(a1, wa.w, acc0[9]);
                            acc0[10] = fmaf(a1, wb.x, acc0[10]);
                            acc0[11] = fmaf(a1, wb.y, acc0[11]);
                            acc1[0]  = fmaf(b0, wa.x, acc1[0]);
                            acc1[1]  = fmaf(b0, wa.y, acc1[1]);
                            acc1[2]  = fmaf(b0, wa.z, acc1[2]);
                            acc1[3]  = fmaf(b0, wa.w, acc1[3]);
                            acc1[4]  = fmaf(b0, wb.x, acc1[4]);
                            acc1[5]  = fmaf(b0, wb.y, acc1[5]);
                            acc1[6]  = fmaf(b1v, wa.x, acc1[6]);
                            acc1[7]  = fmaf(b1v, wa.y, acc1[7]);
                            acc1[8]  = fmaf(b1v, wa.z, acc1[8]);
                            acc1[9]  = fmaf(b1v, wa.w, acc1[9]);
                            acc1[10] = fmaf(b1v, wb.x, acc1[10]);
                            acc1[11] = fmaf(b1v, wb.y, acc1[11]);
                        }
                    }
                }
                int p0 = y * hw + x;
                int zb = ZPART_OFF + g * 6 * npx + p0;
                #pragma unroll
                for (int oc = 0; oc < 6; oc++) {
                    sm[zb + oc * npx]            = acc0[oc];
                    sm[zb + oc * npx + hw]       = acc0[6 + oc];
                    sm[IMG + zb + oc * npx]      = acc1[oc];
                    sm[IMG + zb + oc * npx + hw] = acc1[6 + oc];
                }
            }
            __syncthreads();

            // reduce 8 partial groups + bias -> zbuf (R2 order), both imgs
            {
                const int n = 6 * npx;
                for (int t = tid; t < n; t += TPB) {
                    int oc = (int)__umulhi((unsigned)t, mnpx);
                    int p  = t - oc * npx;
                    float bias = sm[B2S_OFF + oc];
                    #pragma unroll
                    for (int im = 0; im < 2; im++) {
                        float sum = bias;
                        #pragma unroll
                        for (int g = 0; g < 8; g++)
                            sum += sm[im * IMG + ZPART_OFF + (g * 6 + oc) * npx + p];
                        sm[im * IMG + ZBUF_OFF + oc * npx + p] = sum;
                    }
                }
            }
            __syncthreads();
        }

        // ---- bilinear upsample zbuf -> 16x16, subtract from f, both imgs ----
        {
            const float sc2 = (float)hw / 16.0f;
            const int hm = hw - 1;
            for (int idx = tid; idx < 1536; idx += TPB) {
                int c = idx >> 8, p = idx & 255;
                int oy = p >> 4, ox = p & 15;
                float sy = __fadd_rn(__fmul_rn((float)oy + 0.5f, sc2), -0.5f);
                float sx = __fadd_rn(__fmul_rn((float)ox + 0.5f, sc2), -0.5f);
                float fy = floorf(sy), fx = floorf(sx);
                float wy = sy - fy,  wx = sx - fx;
                int y0 = (int)fy, x0 = (int)fx;
                int ya = min(max(y0, 0), hm), yb = min(max(y0 + 1, 0), hm);
                int xa = min(max(x0, 0), hm), xb = min(max(x0 + 1, 0), hm);
                int zc = ZBUF_OFF + c * npx;
                int i00 = ya * hw + xa, i01 = ya * hw + xb;
                int i10 = yb * hw + xa, i11 = yb * hw + xb;
                #pragma unroll
                for (int im = 0; im < 2; im++) {
                    const float* z = sm + im * IMG + zc;
                    float v00 = z[i00], v01 = z[i01];
                    float v10 = z[i10], v11 = z[i11];
                    float va = __fadd_rn(__fmul_rn(v00, 1.0f - wx), __fmul_rn(v01, wx));
                    float vb = __fadd_rn(__fmul_rn(v10, 1.0f - wx), __fmul_rn(v11, wx));
                    float v  = __fadd_rn(__fmul_rn(va, 1.0f - wy), __fmul_rn(vb, wy));
                    sm[im * IMG + F_OFF + idx] -= v;
                }
            }
        }
        __syncthreads();
    }
}

extern "C" void kernel_launch(void* const* d_in, const int* in_sizes, int n_in,
                              void* d_out, int out_size) {
    const float* latents = (const float*)d_in[0];
    const float* w1 = (const float*)d_in[1];
    const float* b1 = (const float*)d_in[2];
    const float* w2 = (const float*)d_in[3];
    const float* b2 = (const float*)d_in[4];
    float* out = (float*)d_out;
    int B2 = in_sizes[0] / 3072;   // two images per CTA
    cudaFuncSetAttribute(var_tok_kernel,
                         cudaFuncAttributeMaxDynamicSharedMemorySize, SMEM_BYTES);
    var_tok_kernel<<<B2, TPB, SMEM_BYTES>>>(latents, w1, b1, w2, b2, out);
}